// round 4
// baseline (speedup 1.0000x reference)
#include <cuda_runtime.h>
#include <math.h>

#define KK 16
#define CC 8
#define TILE 512           // pixels per block (P=4 per thread)
#define NKC 136            // C + K*C output channels
#define PKSTRIDE 64        // padded per-k param record (floats)

// Packed per-k params: [0..7]=bias b=-Linv*mu, [8]=c2, [9..11]=pad,
// [12 + rowf4[i]*4 + j] = Linv[i][j] (row i padded to float4 boundary).
__device__ float g_pk[KK * PKSTRIDE];

__global__ void prep_kernel(const float* __restrict__ scale,
                            const float* __restrict__ mean) {
    int k = threadIdx.x;
    if (k >= KK) return;
    const float* L = scale + k * 64;

    float Linv[8][8];
    for (int j = 0; j < 8; j++)
        for (int i = 0; i < 8; i++) Linv[i][j] = 0.f;

    for (int j = 0; j < 8; j++) {
        for (int i = j; i < 8; i++) {
            float s = (i == j) ? 1.f : 0.f;
            for (int m = j; m < i; m++) s -= L[i * 8 + m] * Linv[m][j];
            Linv[i][j] = s / L[i * 8 + i];
        }
    }

    float logdet = 0.f;
    for (int i = 0; i < 8; i++) logdet += logf(fabsf(L[i * 8 + i]));

    float* pk = g_pk + k * PKSTRIDE;
    for (int i = 0; i < PKSTRIDE; i++) pk[i] = 0.f;

    for (int i = 0; i < 8; i++) {                // bias = -Linv * mu
        float s = 0.f;
        for (int j = 0; j <= i; j++) s -= Linv[i][j] * mean[k * 8 + j];
        pk[i] = s;
    }

    const float LN2PI = 1.8378770664093453f;
    const float LOG2E = 1.4426950408889634f;
    pk[8] = (-logdet - 4.0f * LN2PI) * LOG2E;

    const int rowf4[8] = {0, 1, 2, 3, 4, 6, 8, 10};
    for (int i = 0; i < 8; i++)
        for (int j = 0; j <= i; j++)
            pk[12 + rowf4[i] * 4 + j] = Linv[i][j];
}

__global__ __launch_bounds__(128)
void main_kernel(const float* __restrict__ x, float* __restrict__ out) {
    __shared__ float sPk[KK * PKSTRIDE];   // 4 KB
    __shared__ float xsT[8][TILE];         // 16 KB channel-major x tile
    __shared__ float sg[8][TILE];          // 16 KB gauss (one k-pass of 8)

    const int tid = threadIdx.x;
    for (int i = tid; i < KK * PKSTRIDE; i += 128) sPk[i] = g_pk[i];

    const int T   = blockIdx.x;            // 1024 tiles of 512 pixels
    const int bi  = T >> 7;                // image index (128 tiles/image)
    const int tin = T & 127;               // tile within image

    // Load 4 pixels per thread, stage channel-major, emit identity copy.
    float xv[4][8];
    #pragma unroll
    for (int u = 0; u < 4; u++) {
        int sp = T * TILE + u * 128 + tid;
        const float4* xp = reinterpret_cast<const float4*>(x + (long)sp * 8);
        float4 a = xp[0], b4 = xp[1];
        xv[u][0] = a.x;  xv[u][1] = a.y;  xv[u][2] = a.z;  xv[u][3] = a.w;
        xv[u][4] = b4.x; xv[u][5] = b4.y; xv[u][6] = b4.z; xv[u][7] = b4.w;
        #pragma unroll
        for (int c = 0; c < 8; c++) xsT[c][u * 128 + tid] = xv[u][c];
        float4* op = reinterpret_cast<float4*>(out + (long)sp * NKC);
        op[0] = a;
        op[1] = b4;
    }

    const float NH_LOG2E = -0.7213475204444817f;   // -0.5*log2(e)
    const int warp = tid >> 5, lane = tid & 31;

    #pragma unroll 1
    for (int pass = 0; pass < 2; pass++) {
        __syncthreads();                   // sg free (first iter: also xsT/sPk ready)

        #pragma unroll 1
        for (int kq = 0; kq < 8; kq++) {
            int k = pass * 8 + kq;
            const float* pk = &sPk[k * PKSTRIDE];
            #define LD4(o) (*reinterpret_cast<const float4*>(pk + (o)))
            float4 bA = LD4(0), bB = LD4(4);
            float c2 = LD4(8).x;
            float quad[4], y[4];
            float4 r, s;

            r = LD4(12);
            #pragma unroll
            for (int u = 0; u < 4; u++) {
                y[u] = fmaf(r.x, xv[u][0], bA.x);
                quad[u] = y[u] * y[u];
            }
            r = LD4(16);
            #pragma unroll
            for (int u = 0; u < 4; u++) {
                y[u] = fmaf(r.y, xv[u][1], fmaf(r.x, xv[u][0], bA.y));
                quad[u] = fmaf(y[u], y[u], quad[u]);
            }
            r = LD4(20);
            #pragma unroll
            for (int u = 0; u < 4; u++) {
                y[u] = fmaf(r.z, xv[u][2], fmaf(r.y, xv[u][1],
                       fmaf(r.x, xv[u][0], bA.z)));
                quad[u] = fmaf(y[u], y[u], quad[u]);
            }
            r = LD4(24);
            #pragma unroll
            for (int u = 0; u < 4; u++) {
                y[u] = fmaf(r.w, xv[u][3], fmaf(r.z, xv[u][2],
                       fmaf(r.y, xv[u][1], fmaf(r.x, xv[u][0], bA.w))));
                quad[u] = fmaf(y[u], y[u], quad[u]);
            }
            r = LD4(28); s = LD4(32);
            #pragma unroll
            for (int u = 0; u < 4; u++) {
                y[u] = fmaf(s.x, xv[u][4], fmaf(r.w, xv[u][3],
                       fmaf(r.z, xv[u][2], fmaf(r.y, xv[u][1],
                       fmaf(r.x, xv[u][0], bB.x)))));
                quad[u] = fmaf(y[u], y[u], quad[u]);
            }
            r = LD4(36); s = LD4(40);
            #pragma unroll
            for (int u = 0; u < 4; u++) {
                y[u] = fmaf(s.y, xv[u][5], fmaf(s.x, xv[u][4],
                       fmaf(r.w, xv[u][3], fmaf(r.z, xv[u][2],
                       fmaf(r.y, xv[u][1], fmaf(r.x, xv[u][0], bB.y))))));
                quad[u] = fmaf(y[u], y[u], quad[u]);
            }
            r = LD4(44); s = LD4(48);
            #pragma unroll
            for (int u = 0; u < 4; u++) {
                y[u] = fmaf(s.z, xv[u][6], fmaf(s.y, xv[u][5],
                       fmaf(s.x, xv[u][4], fmaf(r.w, xv[u][3],
                       fmaf(r.z, xv[u][2], fmaf(r.y, xv[u][1],
                       fmaf(r.x, xv[u][0], bB.z)))))));
                quad[u] = fmaf(y[u], y[u], quad[u]);
            }
            r = LD4(52); s = LD4(56);
            #pragma unroll
            for (int u = 0; u < 4; u++) {
                y[u] = fmaf(s.w, xv[u][7], fmaf(s.z, xv[u][6],
                       fmaf(s.y, xv[u][5], fmaf(s.x, xv[u][4],
                       fmaf(r.w, xv[u][3], fmaf(r.z, xv[u][2],
                       fmaf(r.y, xv[u][1], fmaf(r.x, xv[u][0], bB.w))))))));
                quad[u] = fmaf(y[u], y[u], quad[u]);
            }
            #undef LD4

            #pragma unroll
            for (int u = 0; u < 4; u++) {
                float t = fmaf(quad[u], NH_LOG2E, c2);
                t = fmaxf(t, -120.f);
                float fi = rintf(t);
                float f  = t - fi;                 // [-0.5, 0.5]
                float p  = fmaf(f, 0.0013333558f, 0.0096181291f);
                p = fmaf(f, p, 0.0555041087f);
                p = fmaf(f, p, 0.2402265070f);
                p = fmaf(f, p, 0.6931471806f);
                p = fmaf(f, p, 1.0f);
                float sc = __int_as_float(((int)fi + 127) << 23);  // 2^fi
                sg[kq][u * 128 + tid] = p * sc;
            }
        }
        __syncthreads();

        // Epilogue for this pass's 8 k's. Segment (k,c) of this tile maps to
        // 4 output-pixel channel runs: out[((seg*8+bi)*512 + tin*4 + t2)*NKC
        // + 8 + j], j=0..127 — coalesced float4 stores, one 128-run per warp.
        #pragma unroll 1
        for (int t2 = 0; t2 < 4; t2++) {
            float4 xc[8];
            #pragma unroll
            for (int c = 0; c < 8; c++)
                xc[c] = *reinterpret_cast<const float4*>(
                            &xsT[c][t2 * 128 + lane * 4]);
            const int obase = (tin * 4 + t2) * NKC + 8 + lane * 4;
            #pragma unroll
            for (int kk = 0; kk < 2; kk++) {
                int kq = warp * 2 + kk;
                int k  = pass * 8 + kq;
                float4 g4 = *reinterpret_cast<const float4*>(
                                &sg[kq][t2 * 128 + lane * 4]);
                #pragma unroll
                for (int c = 0; c < 8; c++) {
                    int seg = k * 8 + c;
                    int A = (seg * 8 + bi) * (512 * NKC) + obase;
                    float4 o;
                    o.x = g4.x * xc[c].x;
                    o.y = g4.y * xc[c].y;
                    o.z = g4.z * xc[c].z;
                    o.w = g4.w * xc[c].w;
                    *reinterpret_cast<float4*>(out + A) = o;
                }
            }
        }
    }
}

extern "C" void kernel_launch(void* const* d_in, const int* in_sizes, int n_in,
                              void* d_out, int out_size) {
    // Identify inputs by element count: x=4,194,304; scale=1,024; mean=128
    const float* x = nullptr; const float* scale = nullptr; const float* mean = nullptr;
    for (int i = 0; i < n_in; i++) {
        if (in_sizes[i] == 4194304)      x     = (const float*)d_in[i];
        else if (in_sizes[i] == 1024)    scale = (const float*)d_in[i];
        else if (in_sizes[i] == 128)     mean  = (const float*)d_in[i];
    }
    float* out = (float*)d_out;

    prep_kernel<<<1, 32>>>(scale, mean);
    main_kernel<<<1024, 128>>>(x, out);
}

// round 5
// speedup vs baseline: 1.0895x; 1.0895x over previous
#include <cuda_runtime.h>
#include <math.h>

#define KK 16
#define CC 8
#define TILE 128
#define NKC 136            // C + K*C output channels
#define PKSTRIDE 64        // padded per-k param record (floats)

// Packed per-k params: [0..7]=bias b=-Linv*mu, [8]=c2, [9..11]=pad,
// [12 + rowf4[i]*4 + j] = Linv[i][j] (row i padded to float4 boundary).
__device__ float g_pk[KK * PKSTRIDE];

__global__ void prep_kernel(const float* __restrict__ scale,
                            const float* __restrict__ mean) {
    int k = threadIdx.x;
    if (k >= KK) return;
    const float* L = scale + k * 64;

    float Linv[8][8];
    for (int j = 0; j < 8; j++)
        for (int i = 0; i < 8; i++) Linv[i][j] = 0.f;

    // Forward substitution (lower triangle only, matches solve_triangular lower=True)
    for (int j = 0; j < 8; j++) {
        for (int i = j; i < 8; i++) {
            float s = (i == j) ? 1.f : 0.f;
            for (int m = j; m < i; m++) s -= L[i * 8 + m] * Linv[m][j];
            Linv[i][j] = s / L[i * 8 + i];
        }
    }

    float logdet = 0.f;
    for (int i = 0; i < 8; i++) logdet += logf(fabsf(L[i * 8 + i]));

    float* pk = g_pk + k * PKSTRIDE;
    for (int i = 0; i < PKSTRIDE; i++) pk[i] = 0.f;

    for (int i = 0; i < 8; i++) {                // bias = -Linv * mu
        float s = 0.f;
        for (int j = 0; j <= i; j++) s -= Linv[i][j] * mean[k * 8 + j];
        pk[i] = s;
    }

    const float LN2PI = 1.8378770664093453f;
    const float LOG2E = 1.4426950408889634f;
    pk[8] = (-logdet - 4.0f * LN2PI) * LOG2E;   // gauss = 2^(-0.5*log2e*quad + c2)

    const int rowf4[8] = {0, 1, 2, 3, 4, 6, 8, 10};
    for (int i = 0; i < 8; i++)
        for (int j = 0; j <= i; j++)
            pk[12 + rowf4[i] * 4 + j] = Linv[i][j];
}

__global__ __launch_bounds__(128)
void main_kernel(const float* __restrict__ x, float* __restrict__ out) {
    __shared__ float sPk[KK * PKSTRIDE];   // 4 KB
    __shared__ float xsT[8][TILE];         // 4 KB channel-major x tile

    const int tid = threadIdx.x;
    for (int i = tid; i < KK * PKSTRIDE; i += 128) sPk[i] = g_pk[i];

    const int T   = blockIdx.x;            // 4096 tiles of 128 pixels
    const int bi  = T >> 9;                // image index
    const int tin = T & 511;               // tile within image
    const int sp  = T * TILE + tid;        // this thread's staging pixel

    // Coalesced pixel load, channel-major staging, identity copy.
    const float4* xp = reinterpret_cast<const float4*>(x + (long)sp * 8);
    float4 a = xp[0], b4 = xp[1];
    xsT[0][tid] = a.x;  xsT[1][tid] = a.y;
    xsT[2][tid] = a.z;  xsT[3][tid] = a.w;
    xsT[4][tid] = b4.x; xsT[5][tid] = b4.y;
    xsT[6][tid] = b4.z; xsT[7][tid] = b4.w;
    float4* op = reinterpret_cast<float4*>(out + (long)sp * NKC);
    op[0] = a;
    op[1] = b4;
    __syncthreads();

    // Each warp owns 4 mixture components; each thread owns the 4 tile-local
    // pixels (lane*4 .. lane*4+3) that it will store. Compute gauss for
    // (owned k) x (owned pixels) and store directly — no gauss smem round-trip.
    const int warp = tid >> 5, lane = tid & 31;

    float xcc[8][4];                       // x[channel][owned pixel]
    #pragma unroll
    for (int c = 0; c < 8; c++) {
        float4 v = *reinterpret_cast<const float4*>(&xsT[c][lane * 4]);
        xcc[c][0] = v.x; xcc[c][1] = v.y; xcc[c][2] = v.z; xcc[c][3] = v.w;
    }

    const float NH_LOG2E = -0.7213475204444817f;   // -0.5*log2(e)
    const int obase = tin * NKC + 8 + lane * 4;

    #pragma unroll 1
    for (int kk = 0; kk < 4; kk++) {
        const int k = warp * 4 + kk;
        const float* pk = &sPk[k * PKSTRIDE];
        #define LD4(o) (*reinterpret_cast<const float4*>(pk + (o)))
        float4 bA = LD4(0), bB = LD4(4);
        float c2 = LD4(8).x;
        float quad[4], y[4];
        float4 r, s;

        r = LD4(12);
        #pragma unroll
        for (int u = 0; u < 4; u++) {
            y[u] = fmaf(r.x, xcc[0][u], bA.x);
            quad[u] = y[u] * y[u];
        }
        r = LD4(16);
        #pragma unroll
        for (int u = 0; u < 4; u++) {
            y[u] = fmaf(r.y, xcc[1][u], fmaf(r.x, xcc[0][u], bA.y));
            quad[u] = fmaf(y[u], y[u], quad[u]);
        }
        r = LD4(20);
        #pragma unroll
        for (int u = 0; u < 4; u++) {
            y[u] = fmaf(r.z, xcc[2][u], fmaf(r.y, xcc[1][u],
                   fmaf(r.x, xcc[0][u], bA.z)));
            quad[u] = fmaf(y[u], y[u], quad[u]);
        }
        r = LD4(24);
        #pragma unroll
        for (int u = 0; u < 4; u++) {
            y[u] = fmaf(r.w, xcc[3][u], fmaf(r.z, xcc[2][u],
                   fmaf(r.y, xcc[1][u], fmaf(r.x, xcc[0][u], bA.w))));
            quad[u] = fmaf(y[u], y[u], quad[u]);
        }
        r = LD4(28); s = LD4(32);
        #pragma unroll
        for (int u = 0; u < 4; u++) {
            y[u] = fmaf(s.x, xcc[4][u], fmaf(r.w, xcc[3][u],
                   fmaf(r.z, xcc[2][u], fmaf(r.y, xcc[1][u],
                   fmaf(r.x, xcc[0][u], bB.x)))));
            quad[u] = fmaf(y[u], y[u], quad[u]);
        }
        r = LD4(36); s = LD4(40);
        #pragma unroll
        for (int u = 0; u < 4; u++) {
            y[u] = fmaf(s.y, xcc[5][u], fmaf(s.x, xcc[4][u],
                   fmaf(r.w, xcc[3][u], fmaf(r.z, xcc[2][u],
                   fmaf(r.y, xcc[1][u], fmaf(r.x, xcc[0][u], bB.y))))));
            quad[u] = fmaf(y[u], y[u], quad[u]);
        }
        r = LD4(44); s = LD4(48);
        #pragma unroll
        for (int u = 0; u < 4; u++) {
            y[u] = fmaf(s.z, xcc[6][u], fmaf(s.y, xcc[5][u],
                   fmaf(s.x, xcc[4][u], fmaf(r.w, xcc[3][u],
                   fmaf(r.z, xcc[2][u], fmaf(r.y, xcc[1][u],
                   fmaf(r.x, xcc[0][u], bB.z)))))));
            quad[u] = fmaf(y[u], y[u], quad[u]);
        }
        r = LD4(52); s = LD4(56);
        #pragma unroll
        for (int u = 0; u < 4; u++) {
            y[u] = fmaf(s.w, xcc[7][u], fmaf(s.z, xcc[6][u],
                   fmaf(s.y, xcc[5][u], fmaf(s.x, xcc[4][u],
                   fmaf(r.w, xcc[3][u], fmaf(r.z, xcc[2][u],
                   fmaf(r.y, xcc[1][u], fmaf(r.x, xcc[0][u], bB.w))))))));
            quad[u] = fmaf(y[u], y[u], quad[u]);
        }
        #undef LD4

        float g[4];
        #pragma unroll
        for (int u = 0; u < 4; u++) {
            float t = fmaf(quad[u], NH_LOG2E, c2);
            t = fmaxf(t, -120.f);
            float fi = rintf(t);
            float f  = t - fi;                 // [-0.5, 0.5]
            float p  = fmaf(f, 0.0013333558f, 0.0096181291f);
            p = fmaf(f, p, 0.0555041087f);
            p = fmaf(f, p, 0.2402265070f);
            p = fmaf(f, p, 0.6931471806f);
            p = fmaf(f, p, 1.0f);
            float sc = __int_as_float(((int)fi + 127) << 23);  // 2^fi
            g[u] = p * sc;
        }

        // Store 8 channel-segments for this k: each is a contiguous, fully
        // coalesced 512 B run: out[(seg*8+bi)*512*NKC + tin*NKC + 8 + lane*4].
        #pragma unroll
        for (int c = 0; c < 8; c++) {
            int seg = k * 8 + c;
            int A = (seg * 8 + bi) * (512 * NKC) + obase;   // < 2^31
            float4 o;
            o.x = g[0] * xcc[c][0];
            o.y = g[1] * xcc[c][1];
            o.z = g[2] * xcc[c][2];
            o.w = g[3] * xcc[c][3];
            *reinterpret_cast<float4*>(out + A) = o;
        }
    }
}

extern "C" void kernel_launch(void* const* d_in, const int* in_sizes, int n_in,
                              void* d_out, int out_size) {
    // Identify inputs by element count: x=4,194,304; scale=1,024; mean=128
    const float* x = nullptr; const float* scale = nullptr; const float* mean = nullptr;
    for (int i = 0; i < n_in; i++) {
        if (in_sizes[i] == 4194304)      x     = (const float*)d_in[i];
        else if (in_sizes[i] == 1024)    scale = (const float*)d_in[i];
        else if (in_sizes[i] == 128)     mean  = (const float*)d_in[i];
    }
    float* out = (float*)d_out;

    prep_kernel<<<1, 32>>>(scale, mean);
    main_kernel<<<4096, 128>>>(x, out);
}